// round 1
// baseline (speedup 1.0000x reference)
#include <cuda_runtime.h>

#define NUM_USERS 30000
#define NUM_ITEMS 70000
#define NTOT      100000
#define D         128
#define NNZ       1000000
#define NLAYERS   3
#define BATCH     16384
#define FD        512   // D * (1 + NLAYERS), final concat width

// Scratch (no cudaMalloc allowed): 204.8 MB + 51.2 MB device globals.
__device__ float g_final[(size_t)NTOT * FD]; // concat embeddings, slice l = cols [l*128, (l+1)*128)
__device__ float g_Lx[(size_t)NTOT * D];     // SpMM accumulator

// ---------------------------------------------------------------------------
// Init: features = concat(uEmbd, iEmbd) -> g_final slice 0
// ---------------------------------------------------------------------------
__global__ void k_init(const float* __restrict__ uE, const float* __restrict__ iE) {
    int idx = blockIdx.x * blockDim.x + threadIdx.x;  // float4 index over NTOT*D
    const int total = NTOT * (D / 4);
    if (idx >= total) return;
    int r = idx >> 5;          // / (D/4)
    int q = idx & 31;
    float4 v = (r < NUM_USERS)
        ? ((const float4*)uE)[(size_t)r * (D / 4) + q]
        : ((const float4*)iE)[(size_t)(r - NUM_USERS) * (D / 4) + q];
    ((float4*)g_final)[(size_t)r * (FD / 4) + q] = v;
}

__global__ void k_zero_lx() {
    int idx = blockIdx.x * blockDim.x + threadIdx.x;
    const int total = NTOT * (D / 4);
    if (idx >= total) return;
    ((float4*)g_Lx)[idx] = make_float4(0.f, 0.f, 0.f, 0.f);
}

// ---------------------------------------------------------------------------
// SpMM: Lx[r] += v * features[c], warp per edge, float4 per lane (128 floats)
// ---------------------------------------------------------------------------
__global__ void k_spmm(const int* __restrict__ rows, const int* __restrict__ cols,
                       const float* __restrict__ vals, int layer) {
    int e = blockIdx.x * (blockDim.x >> 5) + (threadIdx.x >> 5);
    if (e >= NNZ) return;
    int lane = threadIdx.x & 31;
    int r = rows[e];
    int c = cols[e];
    float v = vals[e];
    const float4* src = (const float4*)(g_final + (size_t)c * FD + layer * D);
    float4 x = src[lane];                 // 32 lanes x 16B = whole 128-float row
    float* dst = g_Lx + (size_t)r * D + lane * 4;
    atomicAdd(dst + 0, v * x.x);
    atomicAdd(dst + 1, v * x.y);
    atomicAdd(dst + 2, v * x.z);
    atomicAdd(dst + 3, v * x.w);
}

// ---------------------------------------------------------------------------
// Fused dual-GEMM + bias + leaky_relu + L2-normalize.
//   c = [Lx + f ; Lx * f]  (K = 256)
//   out = leaky( c @ [Wlin; Wint] + blin + bint ); out /= max(||out||, eps)
// Block: 512 threads, tile = 64 rows x 128 cols. Warp w -> rows 4w..4w+3,
// lane j -> cols 4j..4j+3 (full row inside one warp -> shuffle row-norm).
// smem: W 256x128 (128KB) + C 64x256 (64KB) = 192KB dynamic.
// ---------------------------------------------------------------------------
__global__ void k_gemm(const float* __restrict__ Wlin, const float* __restrict__ blin,
                       const float* __restrict__ Wint, const float* __restrict__ bint,
                       int layer) {
    extern __shared__ float sh[];
    float* sW = sh;               // [256][128]
    float* sC = sh + 256 * 128;   // [64][256]

    int tid = threadIdx.x;  // 0..511
    int rbase = blockIdx.x * 64;
    const float* WL = Wlin + (size_t)layer * D * D;
    const float* WI = Wint + (size_t)layer * D * D;

    // Load combined weight [256][128]
    for (int i = tid; i < 256 * 32; i += 512) {   // float4 granularity
        int k = i >> 5;
        int q = i & 31;
        const float4* srcW = (k < 128) ? (const float4*)(WL + (size_t)k * 128)
                                       : (const float4*)(WI + (size_t)(k - 128) * 128);
        ((float4*)sW)[i] = srcW[q];
    }
    // Load C tile: a = Lx + f, b = Lx * f
    for (int i = tid; i < 64 * 32; i += 512) {    // float4 granularity
        int rr = i >> 5;
        int q = i & 31;
        int r = rbase + rr;
        float4 lx = make_float4(0.f, 0.f, 0.f, 0.f), f = lx;
        if (r < NTOT) {
            lx = ((const float4*)(g_Lx + (size_t)r * D))[q];
            f  = ((const float4*)(g_final + (size_t)r * FD + layer * D))[q];
        }
        float4 a = make_float4(lx.x + f.x, lx.y + f.y, lx.z + f.z, lx.w + f.w);
        float4 b = make_float4(lx.x * f.x, lx.y * f.y, lx.z * f.z, lx.w * f.w);
        ((float4*)(sC + rr * 256))[q]      = a;
        ((float4*)(sC + rr * 256 + 128))[q] = b;
    }
    __syncthreads();

    int w = tid >> 5;
    int lane = tid & 31;
    int j0 = lane * 4;
    int r0 = w * 4;  // local row base

    float4 bias;
    {
        const float* bl = blin + (size_t)layer * D;
        const float* bi = bint + (size_t)layer * D;
        bias.x = bl[j0 + 0] + bi[j0 + 0];
        bias.y = bl[j0 + 1] + bi[j0 + 1];
        bias.z = bl[j0 + 2] + bi[j0 + 2];
        bias.w = bl[j0 + 3] + bi[j0 + 3];
    }
    float4 acc0 = bias, acc1 = bias, acc2 = bias, acc3 = bias;

    #pragma unroll 8
    for (int k = 0; k < 256; k += 4) {
        float4 w0 = *(const float4*)(sW + (k + 0) * 128 + j0);
        float4 w1 = *(const float4*)(sW + (k + 1) * 128 + j0);
        float4 w2 = *(const float4*)(sW + (k + 2) * 128 + j0);
        float4 w3 = *(const float4*)(sW + (k + 3) * 128 + j0);

        float4 c0 = *(const float4*)(sC + (r0 + 0) * 256 + k);
        float4 c1 = *(const float4*)(sC + (r0 + 1) * 256 + k);
        float4 c2 = *(const float4*)(sC + (r0 + 2) * 256 + k);
        float4 c3 = *(const float4*)(sC + (r0 + 3) * 256 + k);

        acc0.x += c0.x * w0.x + c0.y * w1.x + c0.z * w2.x + c0.w * w3.x;
        acc0.y += c0.x * w0.y + c0.y * w1.y + c0.z * w2.y + c0.w * w3.y;
        acc0.z += c0.x * w0.z + c0.y * w1.z + c0.z * w2.z + c0.w * w3.z;
        acc0.w += c0.x * w0.w + c0.y * w1.w + c0.z * w2.w + c0.w * w3.w;

        acc1.x += c1.x * w0.x + c1.y * w1.x + c1.z * w2.x + c1.w * w3.x;
        acc1.y += c1.x * w0.y + c1.y * w1.y + c1.z * w2.y + c1.w * w3.y;
        acc1.z += c1.x * w0.z + c1.y * w1.z + c1.z * w2.z + c1.w * w3.z;
        acc1.w += c1.x * w0.w + c1.y * w1.w + c1.z * w2.w + c1.w * w3.w;

        acc2.x += c2.x * w0.x + c2.y * w1.x + c2.z * w2.x + c2.w * w3.x;
        acc2.y += c2.x * w0.y + c2.y * w1.y + c2.z * w2.y + c2.w * w3.y;
        acc2.z += c2.x * w0.z + c2.y * w1.z + c2.z * w2.z + c2.w * w3.z;
        acc2.w += c2.x * w0.w + c2.y * w1.w + c2.z * w2.w + c2.w * w3.w;

        acc3.x += c3.x * w0.x + c3.y * w1.x + c3.z * w2.x + c3.w * w3.x;
        acc3.y += c3.x * w0.y + c3.y * w1.y + c3.z * w2.y + c3.w * w3.y;
        acc3.z += c3.x * w0.z + c3.y * w1.z + c3.z * w2.z + c3.w * w3.z;
        acc3.w += c3.x * w0.w + c3.y * w1.w + c3.z * w2.w + c3.w * w3.w;
    }

    // Epilogue: leaky_relu -> row L2-norm (whole row inside this warp) -> store
    float4 accs[4] = {acc0, acc1, acc2, acc3};
    #pragma unroll
    for (int rr = 0; rr < 4; rr++) {
        float4 x = accs[rr];
        x.x = x.x > 0.f ? x.x : 0.01f * x.x;
        x.y = x.y > 0.f ? x.y : 0.01f * x.y;
        x.z = x.z > 0.f ? x.z : 0.01f * x.z;
        x.w = x.w > 0.f ? x.w : 0.01f * x.w;
        float ss = x.x * x.x + x.y * x.y + x.z * x.z + x.w * x.w;
        #pragma unroll
        for (int o = 16; o > 0; o >>= 1)
            ss += __shfl_xor_sync(0xffffffffu, ss, o);
        float scale = 1.0f / fmaxf(sqrtf(ss), 1e-12f);
        x.x *= scale; x.y *= scale; x.z *= scale; x.w *= scale;
        int rg = rbase + r0 + rr;
        if (rg < NTOT)
            *(float4*)(g_final + (size_t)rg * FD + (layer + 1) * D + j0) = x;
    }
}

// ---------------------------------------------------------------------------
// Final: out[b] = dot(finalEmbd[u], finalEmbd[i + NUM_USERS]) over 512 dims.
// Warp per pair.
// ---------------------------------------------------------------------------
__global__ void k_dot(const int* __restrict__ uIdx, const int* __restrict__ iIdx,
                      float* __restrict__ out) {
    int b = blockIdx.x * (blockDim.x >> 5) + (threadIdx.x >> 5);
    if (b >= BATCH) return;
    int lane = threadIdx.x & 31;
    int u = uIdx[b];
    int it = iIdx[b] + NUM_USERS;
    const float4* pu = (const float4*)(g_final + (size_t)u * FD);
    const float4* pi = (const float4*)(g_final + (size_t)it * FD);
    float s = 0.f;
    #pragma unroll
    for (int q = 0; q < 4; q++) {
        float4 a = pu[lane + 32 * q];
        float4 c = pi[lane + 32 * q];
        s += a.x * c.x + a.y * c.y + a.z * c.z + a.w * c.w;
    }
    #pragma unroll
    for (int o = 16; o > 0; o >>= 1)
        s += __shfl_xor_sync(0xffffffffu, s, o);
    if (lane == 0) out[b] = s;
}

// ---------------------------------------------------------------------------
extern "C" void kernel_launch(void* const* d_in, const int* in_sizes, int n_in,
                              void* d_out, int out_size) {
    const int*   userIdx = (const int*)d_in[0];
    const int*   itemIdx = (const int*)d_in[1];
    const int*   rows    = (const int*)d_in[2];
    const int*   cols    = (const int*)d_in[3];
    const float* vals    = (const float*)d_in[4];
    const float* uE      = (const float*)d_in[5];
    const float* iE      = (const float*)d_in[6];
    const float* Wlin    = (const float*)d_in[7];
    const float* blin    = (const float*)d_in[8];
    const float* Wint    = (const float*)d_in[9];
    const float* bint    = (const float*)d_in[10];
    float* out = (float*)d_out;

    const int smem_gemm = (256 * 128 + 64 * 256) * (int)sizeof(float);  // 192 KB
    cudaFuncSetAttribute(k_gemm, cudaFuncAttributeMaxDynamicSharedMemorySize, smem_gemm);

    const int vec_total = NTOT * (D / 4);
    k_init<<<(vec_total + 255) / 256, 256>>>(uE, iE);

    for (int l = 0; l < NLAYERS; l++) {
        k_zero_lx<<<(vec_total + 255) / 256, 256>>>();
        k_spmm<<<NNZ / 8, 256>>>(rows, cols, vals, l);
        k_gemm<<<(NTOT + 63) / 64, 512, smem_gemm>>>(Wlin, blin, Wint, bint, l);
    }

    k_dot<<<(BATCH + 7) / 8, 256>>>(userIdx, itemIdx, out);
}

// round 2
// speedup vs baseline: 1.5865x; 1.5865x over previous
#include <cuda_runtime.h>

#define NUM_USERS 30000
#define NUM_ITEMS 70000
#define NTOT      100000
#define D         128
#define NNZ       1000000
#define NLAYERS   3
#define BATCH     16384
#define FD        512   // D * (1 + NLAYERS)

// Scratch (no cudaMalloc allowed)
__device__ float g_final[(size_t)NTOT * FD]; // concat embeddings, slice l = cols [l*128,(l+1)*128)
__device__ float g_Lx[(size_t)NTOT * D];     // SpMM result
__device__ int   g_cnt[NTOT];
__device__ int   g_start[NTOT + 1];
__device__ int   g_cursor[NTOT];
__device__ int   g_ecol[NNZ];
__device__ float g_eval[NNZ];

// ---------------------------------------------------------------------------
// Init: features = concat(uEmbd, iEmbd) -> g_final slice 0
// ---------------------------------------------------------------------------
__global__ void k_init(const float* __restrict__ uE, const float* __restrict__ iE) {
    int idx = blockIdx.x * blockDim.x + threadIdx.x;
    const int total = NTOT * (D / 4);
    if (idx >= total) return;
    int r = idx >> 5;
    int q = idx & 31;
    float4 v = (r < NUM_USERS)
        ? ((const float4*)uE)[(size_t)r * (D / 4) + q]
        : ((const float4*)iE)[(size_t)(r - NUM_USERS) * (D / 4) + q];
    ((float4*)g_final)[(size_t)r * (FD / 4) + q] = v;
}

// ---------------------------------------------------------------------------
// CSR build (once per launch)
// ---------------------------------------------------------------------------
__global__ void k_zero_cnt() {
    int i = blockIdx.x * blockDim.x + threadIdx.x;
    if (i < NTOT) g_cnt[i] = 0;
}

__global__ void k_count(const int* __restrict__ rows) {
    int e = blockIdx.x * blockDim.x + threadIdx.x;
    if (e < NNZ) atomicAdd(&g_cnt[rows[e]], 1);
}

// Single-block exclusive scan of g_cnt -> g_start / g_cursor
__global__ void k_scan() {
    __shared__ int sh[1024];
    const int CHUNK = (NTOT + 1023) / 1024;  // 98
    int t = threadIdx.x;
    int base = t * CHUNK;
    int sum = 0;
    #pragma unroll 4
    for (int i = 0; i < CHUNK; i++) {
        int idx = base + i;
        if (idx < NTOT) sum += g_cnt[idx];
    }
    sh[t] = sum;
    __syncthreads();
    for (int d = 1; d < 1024; d <<= 1) {
        int v = 0;
        if (t >= d) v = sh[t - d];
        __syncthreads();
        if (t >= d) sh[t] += v;
        __syncthreads();
    }
    int run = (t == 0) ? 0 : sh[t - 1];
    for (int i = 0; i < CHUNK; i++) {
        int idx = base + i;
        if (idx < NTOT) {
            g_start[idx] = run;
            g_cursor[idx] = run;
            run += g_cnt[idx];
        }
    }
    if (t == 0) g_start[NTOT] = NNZ;
}

__global__ void k_scatter(const int* __restrict__ rows, const int* __restrict__ cols,
                          const float* __restrict__ vals) {
    int e = blockIdx.x * blockDim.x + threadIdx.x;
    if (e >= NNZ) return;
    int p = atomicAdd(&g_cursor[rows[e]], 1);
    g_ecol[p] = cols[e];
    g_eval[p] = vals[e];
}

// ---------------------------------------------------------------------------
// SpMM gather: warp per row, no atomics. Lx[r] = sum_e v_e * f[c_e]
// ---------------------------------------------------------------------------
__global__ void k_spmm_csr(int layer) {
    int r = blockIdx.x * (blockDim.x >> 5) + (threadIdx.x >> 5);
    if (r >= NTOT) return;
    int lane = threadIdx.x & 31;
    int s = g_start[r];
    int e = g_start[r + 1];
    float4 acc = make_float4(0.f, 0.f, 0.f, 0.f);
    for (int base = s; base < e; base += 32) {
        int idx = base + lane;
        int c = 0; float v = 0.f;
        if (idx < e) { c = g_ecol[idx]; v = g_eval[idx]; }
        int cnt = min(32, e - base);
        for (int j = 0; j < cnt; j++) {
            int   cj = __shfl_sync(0xffffffffu, c, j);
            float vj = __shfl_sync(0xffffffffu, v, j);
            float4 x = ((const float4*)(g_final + (size_t)cj * FD + layer * D))[lane];
            acc.x += vj * x.x; acc.y += vj * x.y;
            acc.z += vj * x.z; acc.w += vj * x.w;
        }
    }
    ((float4*)(g_Lx + (size_t)r * D))[lane] = acc;
}

// ---------------------------------------------------------------------------
// Fused dual-GEMM + bias + leaky_relu + L2-normalize.
//   out = leaky( (Lx+f)@Wlin + (Lx*f)@Wint + blin + bint ); row-normalize.
// Block: 512 threads, 128 rows x 128 cols. Warp w -> rows 8w..8w+7, lane -> 4 cols.
// Two K-phases: phase0 = Wlin on sA, phase1 = Wint on sB (accumulate into same accs).
// smem: sW 64KB + sA 64KB + sB 64KB = 192KB.
// ---------------------------------------------------------------------------
__global__ void k_gemm(const float* __restrict__ Wlin, const float* __restrict__ blin,
                       const float* __restrict__ Wint, const float* __restrict__ bint,
                       int layer) {
    extern __shared__ float sh[];
    float* sW = sh;                 // [128][128]
    float* sA = sh + 128 * 128;     // [128][128]  Lx + f
    float* sB = sA + 128 * 128;     // [128][128]  Lx * f

    int tid = threadIdx.x;
    int rbase = blockIdx.x * 128;
    const float* WL = Wlin + (size_t)layer * D * D;
    const float* WI = Wint + (size_t)layer * D * D;

    // Load C tiles
    for (int i = tid; i < 128 * 32; i += 512) {
        int rr = i >> 5;
        int q = i & 31;
        int r = rbase + rr;
        float4 lx = make_float4(0.f, 0.f, 0.f, 0.f), f = lx;
        if (r < NTOT) {
            lx = ((const float4*)(g_Lx + (size_t)r * D))[q];
            f  = ((const float4*)(g_final + (size_t)r * FD + layer * D))[q];
        }
        ((float4*)(sA + rr * 128))[q] = make_float4(lx.x + f.x, lx.y + f.y, lx.z + f.z, lx.w + f.w);
        ((float4*)(sB + rr * 128))[q] = make_float4(lx.x * f.x, lx.y * f.y, lx.z * f.z, lx.w * f.w);
    }

    int w = tid >> 5;
    int lane = tid & 31;
    int j0 = lane * 4;
    int r0 = w * 8;  // local row base (8 rows per warp)

    float4 bias;
    {
        const float* bl = blin + (size_t)layer * D;
        const float* bi = bint + (size_t)layer * D;
        bias.x = bl[j0 + 0] + bi[j0 + 0];
        bias.y = bl[j0 + 1] + bi[j0 + 1];
        bias.z = bl[j0 + 2] + bi[j0 + 2];
        bias.w = bl[j0 + 3] + bi[j0 + 3];
    }
    float4 acc[8];
    #pragma unroll
    for (int rr = 0; rr < 8; rr++) acc[rr] = bias;

    #pragma unroll
    for (int phase = 0; phase < 2; phase++) {
        __syncthreads();  // C stores visible (p0) / prior-phase sW reads done (p1)
        const float* Wg = (phase == 0) ? WL : WI;
        for (int i = tid; i < 128 * 32; i += 512)
            ((float4*)sW)[i] = ((const float4*)Wg)[i];
        __syncthreads();
        const float* sC = (phase == 0) ? sA : sB;

        #pragma unroll 4
        for (int k = 0; k < 128; k += 4) {
            float4 w0 = *(const float4*)(sW + (k + 0) * 128 + j0);
            float4 w1 = *(const float4*)(sW + (k + 1) * 128 + j0);
            float4 w2 = *(const float4*)(sW + (k + 2) * 128 + j0);
            float4 w3 = *(const float4*)(sW + (k + 3) * 128 + j0);
            #pragma unroll
            for (int rr = 0; rr < 8; rr++) {
                float4 c = *(const float4*)(sC + (r0 + rr) * 128 + k);  // warp-uniform broadcast
                acc[rr].x += c.x * w0.x + c.y * w1.x + c.z * w2.x + c.w * w3.x;
                acc[rr].y += c.x * w0.y + c.y * w1.y + c.z * w2.y + c.w * w3.y;
                acc[rr].z += c.x * w0.z + c.y * w1.z + c.z * w2.z + c.w * w3.z;
                acc[rr].w += c.x * w0.w + c.y * w1.w + c.z * w2.w + c.w * w3.w;
            }
        }
    }

    // Epilogue: leaky_relu -> row L2-norm (row fully inside warp) -> store
    #pragma unroll
    for (int rr = 0; rr < 8; rr++) {
        float4 x = acc[rr];
        x.x = x.x > 0.f ? x.x : 0.01f * x.x;
        x.y = x.y > 0.f ? x.y : 0.01f * x.y;
        x.z = x.z > 0.f ? x.z : 0.01f * x.z;
        x.w = x.w > 0.f ? x.w : 0.01f * x.w;
        float ss = x.x * x.x + x.y * x.y + x.z * x.z + x.w * x.w;
        #pragma unroll
        for (int o = 16; o > 0; o >>= 1)
            ss += __shfl_xor_sync(0xffffffffu, ss, o);
        float scale = 1.0f / fmaxf(sqrtf(ss), 1e-12f);
        x.x *= scale; x.y *= scale; x.z *= scale; x.w *= scale;
        int rg = rbase + r0 + rr;
        if (rg < NTOT)
            *(float4*)(g_final + (size_t)rg * FD + (layer + 1) * D + j0) = x;
    }
}

// ---------------------------------------------------------------------------
// Final: out[b] = dot(finalEmbd[u], finalEmbd[i + NUM_USERS]) over 512 dims.
// ---------------------------------------------------------------------------
__global__ void k_dot(const int* __restrict__ uIdx, const int* __restrict__ iIdx,
                      float* __restrict__ out) {
    int b = blockIdx.x * (blockDim.x >> 5) + (threadIdx.x >> 5);
    if (b >= BATCH) return;
    int lane = threadIdx.x & 31;
    int u = uIdx[b];
    int it = iIdx[b] + NUM_USERS;
    const float4* pu = (const float4*)(g_final + (size_t)u * FD);
    const float4* pi = (const float4*)(g_final + (size_t)it * FD);
    float s = 0.f;
    #pragma unroll
    for (int q = 0; q < 4; q++) {
        float4 a = pu[lane + 32 * q];
        float4 c = pi[lane + 32 * q];
        s += a.x * c.x + a.y * c.y + a.z * c.z + a.w * c.w;
    }
    #pragma unroll
    for (int o = 16; o > 0; o >>= 1)
        s += __shfl_xor_sync(0xffffffffu, s, o);
    if (lane == 0) out[b] = s;
}

// ---------------------------------------------------------------------------
extern "C" void kernel_launch(void* const* d_in, const int* in_sizes, int n_in,
                              void* d_out, int out_size) {
    const int*   userIdx = (const int*)d_in[0];
    const int*   itemIdx = (const int*)d_in[1];
    const int*   rows    = (const int*)d_in[2];
    const int*   cols    = (const int*)d_in[3];
    const float* vals    = (const float*)d_in[4];
    const float* uE      = (const float*)d_in[5];
    const float* iE      = (const float*)d_in[6];
    const float* Wlin    = (const float*)d_in[7];
    const float* blin    = (const float*)d_in[8];
    const float* Wint    = (const float*)d_in[9];
    const float* bint    = (const float*)d_in[10];
    float* out = (float*)d_out;

    const int smem_gemm = 3 * 128 * 128 * (int)sizeof(float);  // 192 KB
    cudaFuncSetAttribute(k_gemm, cudaFuncAttributeMaxDynamicSharedMemorySize, smem_gemm);

    const int vec_total = NTOT * (D / 4);
    k_init<<<(vec_total + 255) / 256, 256>>>(uE, iE);

    // CSR build (once per launch)
    k_zero_cnt<<<(NTOT + 255) / 256, 256>>>();
    k_count<<<(NNZ + 255) / 256, 256>>>(rows);
    k_scan<<<1, 1024>>>();
    k_scatter<<<(NNZ + 255) / 256, 256>>>(rows, cols, vals);

    for (int l = 0; l < NLAYERS; l++) {
        k_spmm_csr<<<(NTOT + 7) / 8, 256>>>(l);
        k_gemm<<<(NTOT + 127) / 128, 512, smem_gemm>>>(Wlin, blin, Wint, bint, l);
    }

    k_dot<<<(BATCH + 7) / 8, 256>>>(userIdx, itemIdx, out);
}

// round 3
// speedup vs baseline: 1.8682x; 1.1775x over previous
#include <cuda_runtime.h>

#define NUM_USERS 30000
#define NUM_ITEMS 70000
#define NTOT      100000
#define D         128
#define NNZ       1000000
#define NLAYERS   3
#define BATCH     16384
#define FD        512   // D * (1 + NLAYERS)

#define SCAN_BS   1024                              // elements per scan block
#define SCAN_NB   ((NTOT + SCAN_BS - 1) / SCAN_BS)  // 98

// Scratch (no cudaMalloc allowed)
__device__ float g_final[(size_t)NTOT * FD]; // concat embeddings, slice l = cols [l*128,(l+1)*128)
__device__ float g_Lx[(size_t)NTOT * D];     // SpMM result
__device__ int   g_cnt[NTOT];
__device__ int   g_start[NTOT + 1];
__device__ int   g_cursor[NTOT];
__device__ int   g_ecol[NNZ];
__device__ float g_eval[NNZ];
__device__ int   g_bsum[SCAN_NB];
__device__ int   g_boff[SCAN_NB];

// ---------------------------------------------------------------------------
// Init: features = concat(uEmbd, iEmbd) -> g_final slice 0
// ---------------------------------------------------------------------------
__global__ void k_init(const float* __restrict__ uE, const float* __restrict__ iE) {
    int idx = blockIdx.x * blockDim.x + threadIdx.x;
    const int total = NTOT * (D / 4);
    if (idx >= total) return;
    int r = idx >> 5;
    int q = idx & 31;
    float4 v = (r < NUM_USERS)
        ? ((const float4*)uE)[(size_t)r * (D / 4) + q]
        : ((const float4*)iE)[(size_t)(r - NUM_USERS) * (D / 4) + q];
    ((float4*)g_final)[(size_t)r * (FD / 4) + q] = v;
}

// ---------------------------------------------------------------------------
// CSR build (once per launch)
// ---------------------------------------------------------------------------
__global__ void k_zero_cnt() {
    int i = blockIdx.x * blockDim.x + threadIdx.x;
    if (i < NTOT) g_cnt[i] = 0;
}

__global__ void k_count(const int* __restrict__ rows) {
    int e = blockIdx.x * blockDim.x + threadIdx.x;
    if (e < NNZ) atomicAdd(&g_cnt[rows[e]], 1);
}

// Phase 1: per-block local exclusive scan of g_cnt -> g_start, block totals -> g_bsum
// 256 threads x 4 elements = 1024 per block.
__global__ void k_scan1() {
    __shared__ int wsum[8];
    int t = threadIdx.x;
    int base = blockIdx.x * SCAN_BS + t * 4;
    int c0 = 0, c1 = 0, c2 = 0, c3 = 0;
    if (base + 3 < NTOT) {
        int4 c = *(const int4*)(g_cnt + base);
        c0 = c.x; c1 = c.y; c2 = c.z; c3 = c.w;
    } else {
        if (base + 0 < NTOT) c0 = g_cnt[base + 0];
        if (base + 1 < NTOT) c1 = g_cnt[base + 1];
        if (base + 2 < NTOT) c2 = g_cnt[base + 2];
        if (base + 3 < NTOT) c3 = g_cnt[base + 3];
    }
    int tot = c0 + c1 + c2 + c3;
    // warp inclusive scan of per-thread totals
    int inc = tot;
    #pragma unroll
    for (int d = 1; d < 32; d <<= 1) {
        int v = __shfl_up_sync(0xffffffffu, inc, d);
        if ((t & 31) >= d) inc += v;
    }
    if ((t & 31) == 31) wsum[t >> 5] = inc;
    __syncthreads();
    if (t < 8) {
        int v = wsum[t];
        int wi = v;
        #pragma unroll
        for (int d = 1; d < 8; d <<= 1) {
            int u = __shfl_up_sync(0xffu, wi, d);
            if (t >= d) wi += u;
        }
        wsum[t] = wi - v;  // exclusive warp offsets
        if (t == 7 && threadIdx.x < 8) g_bsum[blockIdx.x] = wi;  // block total
    }
    __syncthreads();
    int off = wsum[t >> 5] + (inc - tot);  // exclusive prefix for this thread
    if (base + 0 < NTOT) g_start[base + 0] = off;
    if (base + 1 < NTOT) g_start[base + 1] = off + c0;
    if (base + 2 < NTOT) g_start[base + 2] = off + c0 + c1;
    if (base + 3 < NTOT) g_start[base + 3] = off + c0 + c1 + c2;
}

// Phase 2: exclusive scan of SCAN_NB block sums (1 block, 128 threads)
__global__ void k_scan2() {
    __shared__ int wsum[4];
    int t = threadIdx.x;
    int v = (t < SCAN_NB) ? g_bsum[t] : 0;
    int inc = v;
    #pragma unroll
    for (int d = 1; d < 32; d <<= 1) {
        int u = __shfl_up_sync(0xffffffffu, inc, d);
        if ((t & 31) >= d) inc += u;
    }
    if ((t & 31) == 31) wsum[t >> 5] = inc;
    __syncthreads();
    if (t < 4) {
        int w = wsum[t];
        int wi = w;
        #pragma unroll
        for (int d = 1; d < 4; d <<= 1) {
            int u = __shfl_up_sync(0xfu, wi, d);
            if (t >= d) wi += u;
        }
        wsum[t] = wi - w;
    }
    __syncthreads();
    if (t < SCAN_NB) g_boff[t] = wsum[t >> 5] + (inc - v);
    if (t == 0) g_start[NTOT] = NNZ;
}

// Phase 3: add block offsets, mirror to cursor
__global__ void k_scan3() {
    int i = blockIdx.x * blockDim.x + threadIdx.x;
    if (i >= NTOT) return;
    int s = g_start[i] + g_boff[i / SCAN_BS];
    g_start[i] = s;
    g_cursor[i] = s;
}

__global__ void k_scatter(const int* __restrict__ rows, const int* __restrict__ cols,
                          const float* __restrict__ vals) {
    int e = blockIdx.x * blockDim.x + threadIdx.x;
    if (e >= NNZ) return;
    int p = atomicAdd(&g_cursor[rows[e]], 1);
    g_ecol[p] = cols[e];
    g_eval[p] = vals[e];
}

// ---------------------------------------------------------------------------
// SpMM gather: warp per row, no atomics, 4-edge unroll for MLP.
// ---------------------------------------------------------------------------
__global__ void k_spmm_csr(int layer) {
    int r = blockIdx.x * (blockDim.x >> 5) + (threadIdx.x >> 5);
    if (r >= NTOT) return;
    int lane = threadIdx.x & 31;
    int s = g_start[r];
    int e = g_start[r + 1];
    const float* fb = g_final + (size_t)layer * D;
    float4 acc = make_float4(0.f, 0.f, 0.f, 0.f);
    for (int base = s; base < e; base += 32) {
        int idx = base + lane;
        int c = 0; float v = 0.f;
        if (idx < e) { c = g_ecol[idx]; v = g_eval[idx]; }
        int cnt = min(32, e - base);
        int j = 0;
        for (; j + 4 <= cnt; j += 4) {
            int   c0 = __shfl_sync(0xffffffffu, c, j + 0);
            int   c1 = __shfl_sync(0xffffffffu, c, j + 1);
            int   c2 = __shfl_sync(0xffffffffu, c, j + 2);
            int   c3 = __shfl_sync(0xffffffffu, c, j + 3);
            float v0 = __shfl_sync(0xffffffffu, v, j + 0);
            float v1 = __shfl_sync(0xffffffffu, v, j + 1);
            float v2 = __shfl_sync(0xffffffffu, v, j + 2);
            float v3 = __shfl_sync(0xffffffffu, v, j + 3);
            float4 x0 = ((const float4*)(fb + (size_t)c0 * FD))[lane];
            float4 x1 = ((const float4*)(fb + (size_t)c1 * FD))[lane];
            float4 x2 = ((const float4*)(fb + (size_t)c2 * FD))[lane];
            float4 x3 = ((const float4*)(fb + (size_t)c3 * FD))[lane];
            acc.x += v0 * x0.x + v1 * x1.x + v2 * x2.x + v3 * x3.x;
            acc.y += v0 * x0.y + v1 * x1.y + v2 * x2.y + v3 * x3.y;
            acc.z += v0 * x0.z + v1 * x1.z + v2 * x2.z + v3 * x3.z;
            acc.w += v0 * x0.w + v1 * x1.w + v2 * x2.w + v3 * x3.w;
        }
        for (; j < cnt; j++) {
            int   cj = __shfl_sync(0xffffffffu, c, j);
            float vj = __shfl_sync(0xffffffffu, v, j);
            float4 x = ((const float4*)(fb + (size_t)cj * FD))[lane];
            acc.x += vj * x.x; acc.y += vj * x.y;
            acc.z += vj * x.z; acc.w += vj * x.w;
        }
    }
    ((float4*)(g_Lx + (size_t)r * D))[lane] = acc;
}

// ---------------------------------------------------------------------------
// Fused dual-GEMM + bias + leaky_relu + L2-normalize. (as round 2)
// ---------------------------------------------------------------------------
__global__ void k_gemm(const float* __restrict__ Wlin, const float* __restrict__ blin,
                       const float* __restrict__ Wint, const float* __restrict__ bint,
                       int layer) {
    extern __shared__ float sh[];
    float* sW = sh;                 // [128][128]
    float* sA = sh + 128 * 128;     // [128][128]  Lx + f
    float* sB = sA + 128 * 128;     // [128][128]  Lx * f

    int tid = threadIdx.x;
    int rbase = blockIdx.x * 128;
    const float* WL = Wlin + (size_t)layer * D * D;
    const float* WI = Wint + (size_t)layer * D * D;

    for (int i = tid; i < 128 * 32; i += 512) {
        int rr = i >> 5;
        int q = i & 31;
        int r = rbase + rr;
        float4 lx = make_float4(0.f, 0.f, 0.f, 0.f), f = lx;
        if (r < NTOT) {
            lx = ((const float4*)(g_Lx + (size_t)r * D))[q];
            f  = ((const float4*)(g_final + (size_t)r * FD + layer * D))[q];
        }
        ((float4*)(sA + rr * 128))[q] = make_float4(lx.x + f.x, lx.y + f.y, lx.z + f.z, lx.w + f.w);
        ((float4*)(sB + rr * 128))[q] = make_float4(lx.x * f.x, lx.y * f.y, lx.z * f.z, lx.w * f.w);
    }

    int w = tid >> 5;
    int lane = tid & 31;
    int j0 = lane * 4;
    int r0 = w * 8;

    float4 bias;
    {
        const float* bl = blin + (size_t)layer * D;
        const float* bi = bint + (size_t)layer * D;
        bias.x = bl[j0 + 0] + bi[j0 + 0];
        bias.y = bl[j0 + 1] + bi[j0 + 1];
        bias.z = bl[j0 + 2] + bi[j0 + 2];
        bias.w = bl[j0 + 3] + bi[j0 + 3];
    }
    float4 acc[8];
    #pragma unroll
    for (int rr = 0; rr < 8; rr++) acc[rr] = bias;

    #pragma unroll
    for (int phase = 0; phase < 2; phase++) {
        __syncthreads();
        const float* Wg = (phase == 0) ? WL : WI;
        for (int i = tid; i < 128 * 32; i += 512)
            ((float4*)sW)[i] = ((const float4*)Wg)[i];
        __syncthreads();
        const float* sC = (phase == 0) ? sA : sB;

        #pragma unroll 4
        for (int k = 0; k < 128; k += 4) {
            float4 w0 = *(const float4*)(sW + (k + 0) * 128 + j0);
            float4 w1 = *(const float4*)(sW + (k + 1) * 128 + j0);
            float4 w2 = *(const float4*)(sW + (k + 2) * 128 + j0);
            float4 w3 = *(const float4*)(sW + (k + 3) * 128 + j0);
            #pragma unroll
            for (int rr = 0; rr < 8; rr++) {
                float4 c = *(const float4*)(sC + (r0 + rr) * 128 + k);
                acc[rr].x += c.x * w0.x + c.y * w1.x + c.z * w2.x + c.w * w3.x;
                acc[rr].y += c.x * w0.y + c.y * w1.y + c.z * w2.y + c.w * w3.y;
                acc[rr].z += c.x * w0.z + c.y * w1.z + c.z * w2.z + c.w * w3.z;
                acc[rr].w += c.x * w0.w + c.y * w1.w + c.z * w2.w + c.w * w3.w;
            }
        }
    }

    #pragma unroll
    for (int rr = 0; rr < 8; rr++) {
        float4 x = acc[rr];
        x.x = x.x > 0.f ? x.x : 0.01f * x.x;
        x.y = x.y > 0.f ? x.y : 0.01f * x.y;
        x.z = x.z > 0.f ? x.z : 0.01f * x.z;
        x.w = x.w > 0.f ? x.w : 0.01f * x.w;
        float ss = x.x * x.x + x.y * x.y + x.z * x.z + x.w * x.w;
        #pragma unroll
        for (int o = 16; o > 0; o >>= 1)
            ss += __shfl_xor_sync(0xffffffffu, ss, o);
        float scale = 1.0f / fmaxf(sqrtf(ss), 1e-12f);
        x.x *= scale; x.y *= scale; x.z *= scale; x.w *= scale;
        int rg = rbase + r0 + rr;
        if (rg < NTOT)
            *(float4*)(g_final + (size_t)rg * FD + (layer + 1) * D + j0) = x;
    }
}

// ---------------------------------------------------------------------------
// Final: out[b] = dot(finalEmbd[u], finalEmbd[i + NUM_USERS]) over 512 dims.
// ---------------------------------------------------------------------------
__global__ void k_dot(const int* __restrict__ uIdx, const int* __restrict__ iIdx,
                      float* __restrict__ out) {
    int b = blockIdx.x * (blockDim.x >> 5) + (threadIdx.x >> 5);
    if (b >= BATCH) return;
    int lane = threadIdx.x & 31;
    int u = uIdx[b];
    int it = iIdx[b] + NUM_USERS;
    const float4* pu = (const float4*)(g_final + (size_t)u * FD);
    const float4* pi = (const float4*)(g_final + (size_t)it * FD);
    float s = 0.f;
    #pragma unroll
    for (int q = 0; q < 4; q++) {
        float4 a = pu[lane + 32 * q];
        float4 c = pi[lane + 32 * q];
        s += a.x * c.x + a.y * c.y + a.z * c.z + a.w * c.w;
    }
    #pragma unroll
    for (int o = 16; o > 0; o >>= 1)
        s += __shfl_xor_sync(0xffffffffu, s, o);
    if (lane == 0) out[b] = s;
}

// ---------------------------------------------------------------------------
extern "C" void kernel_launch(void* const* d_in, const int* in_sizes, int n_in,
                              void* d_out, int out_size) {
    const int*   userIdx = (const int*)d_in[0];
    const int*   itemIdx = (const int*)d_in[1];
    const int*   rows    = (const int*)d_in[2];
    const int*   cols    = (const int*)d_in[3];
    const float* vals    = (const float*)d_in[4];
    const float* uE      = (const float*)d_in[5];
    const float* iE      = (const float*)d_in[6];
    const float* Wlin    = (const float*)d_in[7];
    const float* blin    = (const float*)d_in[8];
    const float* Wint    = (const float*)d_in[9];
    const float* bint    = (const float*)d_in[10];
    float* out = (float*)d_out;

    const int smem_gemm = 3 * 128 * 128 * (int)sizeof(float);  // 192 KB
    cudaFuncSetAttribute(k_gemm, cudaFuncAttributeMaxDynamicSharedMemorySize, smem_gemm);

    const int vec_total = NTOT * (D / 4);
    k_init<<<(vec_total + 255) / 256, 256>>>(uE, iE);

    // CSR build (once per launch)
    k_zero_cnt<<<(NTOT + 255) / 256, 256>>>();
    k_count<<<(NNZ + 255) / 256, 256>>>(rows);
    k_scan1<<<SCAN_NB, 256>>>();
    k_scan2<<<1, 128>>>();
    k_scan3<<<(NTOT + 255) / 256, 256>>>();
    k_scatter<<<(NNZ + 255) / 256, 256>>>(rows, cols, vals);

    for (int l = 0; l < NLAYERS; l++) {
        k_spmm_csr<<<(NTOT + 7) / 8, 256>>>(l);
        k_gemm<<<(NTOT + 127) / 128, 512, smem_gemm>>>(Wlin, blin, Wint, bint, l);
    }

    k_dot<<<(BATCH + 7) / 8, 256>>>(userIdx, itemIdx, out);
}

// round 5
// speedup vs baseline: 2.9650x; 1.5871x over previous
#include <cuda_runtime.h>
#include <cuda_bf16.h>
#include <cstdint>

#define NUM_USERS 30000
#define NUM_ITEMS 70000
#define NTOT      100000
#define D         128
#define NNZ       1000000
#define NLAYERS   3
#define BATCH     16384
#define FD        512   // D * (1 + NLAYERS)

#define SCAN_BS   1024
#define SCAN_NB   ((NTOT + SCAN_BS - 1) / SCAN_BS)  // 98

// Scratch (no cudaMalloc allowed)
__device__ float g_final[(size_t)NTOT * FD];
__device__ float g_Lx[(size_t)NTOT * D];
__device__ int   g_cnt[NTOT];
__device__ int   g_start[NTOT + 1];
__device__ int   g_cursor[NTOT];
__device__ int   g_ecol[NNZ];
__device__ float g_eval[NNZ];
__device__ int   g_bsum[SCAN_NB];
__device__ int   g_boff[SCAN_NB];
// Pre-split, pre-transposed weight images: per (layer, phase{lin,int}, split{hi,mid}):
// B[n][k] bf16 row-major [128][128], packed as u32 pairs (8192 u32 = 32KB each)
__device__ uint32_t g_wimg[3 * 2 * 2 * 8192];

// ======================= mma.sync helpers =======================
__device__ __forceinline__ uint32_t smem_u32(const void* p) {
    uint32_t a;
    asm("{ .reg .u64 t; cvta.to.shared.u64 t, %1; cvt.u32.u64 %0, t; }" : "=r"(a) : "l"(p));
    return a;
}
__device__ __forceinline__ void ldsm4(uint32_t* r, uint32_t addr) {
    asm volatile("ldmatrix.sync.aligned.m8n8.x4.shared.b16 {%0,%1,%2,%3}, [%4];"
                 : "=r"(r[0]), "=r"(r[1]), "=r"(r[2]), "=r"(r[3]) : "r"(addr));
}
__device__ __forceinline__ void mma16816(float* d, const uint32_t* a, uint32_t b0, uint32_t b1) {
    asm volatile(
        "mma.sync.aligned.m16n8k16.row.col.f32.bf16.bf16.f32 "
        "{%0,%1,%2,%3}, {%4,%5,%6,%7}, {%8,%9}, {%0,%1,%2,%3};"
        : "+f"(d[0]), "+f"(d[1]), "+f"(d[2]), "+f"(d[3])
        : "r"(a[0]), "r"(a[1]), "r"(a[2]), "r"(a[3]), "r"(b0), "r"(b1));
}
__device__ __forceinline__ uint32_t pack2(__nv_bfloat16 lo, __nv_bfloat16 hi) {
    return ((uint32_t)__bfloat16_as_ushort(hi) << 16) | (uint32_t)__bfloat16_as_ushort(lo);
}

#define TPITCH_B 272   // tile row pitch in bytes (136 halves): 16B-aligned, conflict-free ldmatrix
#define TILE_B   (128 * TPITCH_B)  // 34816 bytes per [128][128] bf16 tile

// ---------------------------------------------------------------------------
// Init
// ---------------------------------------------------------------------------
__global__ void k_init(const float* __restrict__ uE, const float* __restrict__ iE) {
    int idx = blockIdx.x * blockDim.x + threadIdx.x;
    const int total = NTOT * (D / 4);
    if (idx >= total) return;
    int r = idx >> 5;
    int q = idx & 31;
    float4 v = (r < NUM_USERS)
        ? ((const float4*)uE)[(size_t)r * (D / 4) + q]
        : ((const float4*)iE)[(size_t)(r - NUM_USERS) * (D / 4) + q];
    ((float4*)g_final)[(size_t)r * (FD / 4) + q] = v;
}

// ---------------------------------------------------------------------------
// Weight split/transpose precompute (once). B[n][k] = W[k][n], hi/mid bf16.
// ---------------------------------------------------------------------------
__global__ void k_wsplit(const float* __restrict__ Wlin, const float* __restrict__ Wint) {
    int idx = blockIdx.x * blockDim.x + threadIdx.x;
    const int total = 3 * 2 * 128 * 64;   // (l, p, n, k2)
    if (idx >= total) return;
    int k2 = idx & 63;
    int n  = (idx >> 6) & 127;
    int lp = idx >> 13;
    int p  = lp & 1;
    int l  = lp >> 1;
    int k  = k2 * 2;
    const float* W = (p ? Wint : Wlin) + (size_t)l * D * D;
    float w0 = W[(size_t)k * 128 + n];
    float w1 = W[(size_t)(k + 1) * 128 + n];
    __nv_bfloat16 h0 = __float2bfloat16(w0);
    __nv_bfloat16 h1 = __float2bfloat16(w1);
    __nv_bfloat16 m0 = __float2bfloat16(w0 - __bfloat162float(h0));
    __nv_bfloat16 m1 = __float2bfloat16(w1 - __bfloat162float(h1));
    int baseH = ((l * 2 + p) * 2 + 0) * 8192;
    int baseM = ((l * 2 + p) * 2 + 1) * 8192;
    g_wimg[baseH + n * 64 + k2] = pack2(h0, h1);
    g_wimg[baseM + n * 64 + k2] = pack2(m0, m1);
}

// ---------------------------------------------------------------------------
// CSR build (as round 3)
// ---------------------------------------------------------------------------
__global__ void k_zero_cnt() {
    int i = blockIdx.x * blockDim.x + threadIdx.x;
    if (i < NTOT) g_cnt[i] = 0;
}
__global__ void k_count(const int* __restrict__ rows) {
    int e = blockIdx.x * blockDim.x + threadIdx.x;
    if (e < NNZ) atomicAdd(&g_cnt[rows[e]], 1);
}
__global__ void k_scan1() {
    __shared__ int wsum[8];
    int t = threadIdx.x;
    int base = blockIdx.x * SCAN_BS + t * 4;
    int c0 = 0, c1 = 0, c2 = 0, c3 = 0;
    if (base + 3 < NTOT) {
        int4 c = *(const int4*)(g_cnt + base);
        c0 = c.x; c1 = c.y; c2 = c.z; c3 = c.w;
    } else {
        if (base + 0 < NTOT) c0 = g_cnt[base + 0];
        if (base + 1 < NTOT) c1 = g_cnt[base + 1];
        if (base + 2 < NTOT) c2 = g_cnt[base + 2];
        if (base + 3 < NTOT) c3 = g_cnt[base + 3];
    }
    int tot = c0 + c1 + c2 + c3;
    int inc = tot;
    #pragma unroll
    for (int d = 1; d < 32; d <<= 1) {
        int v = __shfl_up_sync(0xffffffffu, inc, d);
        if ((t & 31) >= d) inc += v;
    }
    if ((t & 31) == 31) wsum[t >> 5] = inc;
    __syncthreads();
    if (t < 8) {
        int v = wsum[t];
        int wi = v;
        #pragma unroll
        for (int d = 1; d < 8; d <<= 1) {
            int u = __shfl_up_sync(0xffu, wi, d);
            if (t >= d) wi += u;
        }
        wsum[t] = wi - v;
        if (t == 7) g_bsum[blockIdx.x] = wi;
    }
    __syncthreads();
    int off = wsum[t >> 5] + (inc - tot);
    if (base + 0 < NTOT) g_start[base + 0] = off;
    if (base + 1 < NTOT) g_start[base + 1] = off + c0;
    if (base + 2 < NTOT) g_start[base + 2] = off + c0 + c1;
    if (base + 3 < NTOT) g_start[base + 3] = off + c0 + c1 + c2;
}
__global__ void k_scan2() {
    __shared__ int wsum[4];
    int t = threadIdx.x;
    int v = (t < SCAN_NB) ? g_bsum[t] : 0;
    int inc = v;
    #pragma unroll
    for (int d = 1; d < 32; d <<= 1) {
        int u = __shfl_up_sync(0xffffffffu, inc, d);
        if ((t & 31) >= d) inc += u;
    }
    if ((t & 31) == 31) wsum[t >> 5] = inc;
    __syncthreads();
    if (t < 4) {
        int w = wsum[t];
        int wi = w;
        #pragma unroll
        for (int d = 1; d < 4; d <<= 1) {
            int u = __shfl_up_sync(0xfu, wi, d);
            if (t >= d) wi += u;
        }
        wsum[t] = wi - w;
    }
    __syncthreads();
    if (t < SCAN_NB) g_boff[t] = wsum[t >> 5] + (inc - v);
    if (t == 0) g_start[NTOT] = NNZ;
}
__global__ void k_scan3() {
    int i = blockIdx.x * blockDim.x + threadIdx.x;
    if (i >= NTOT) return;
    int s = g_start[i] + g_boff[i / SCAN_BS];
    g_start[i] = s;
    g_cursor[i] = s;
}
__global__ void k_scatter(const int* __restrict__ rows, const int* __restrict__ cols,
                          const float* __restrict__ vals) {
    int e = blockIdx.x * blockDim.x + threadIdx.x;
    if (e >= NNZ) return;
    int p = atomicAdd(&g_cursor[rows[e]], 1);
    g_ecol[p] = cols[e];
    g_eval[p] = vals[e];
}

// ---------------------------------------------------------------------------
// SpMM gather (as round 3)
// ---------------------------------------------------------------------------
__global__ void k_spmm_csr(int layer) {
    int r = blockIdx.x * (blockDim.x >> 5) + (threadIdx.x >> 5);
    if (r >= NTOT) return;
    int lane = threadIdx.x & 31;
    int s = g_start[r];
    int e = g_start[r + 1];
    const float* fb = g_final + (size_t)layer * D;
    float4 acc = make_float4(0.f, 0.f, 0.f, 0.f);
    for (int base = s; base < e; base += 32) {
        int idx = base + lane;
        int c = 0; float v = 0.f;
        if (idx < e) { c = g_ecol[idx]; v = g_eval[idx]; }
        int cnt = min(32, e - base);
        int j = 0;
        for (; j + 4 <= cnt; j += 4) {
            int   c0 = __shfl_sync(0xffffffffu, c, j + 0);
            int   c1 = __shfl_sync(0xffffffffu, c, j + 1);
            int   c2 = __shfl_sync(0xffffffffu, c, j + 2);
            int   c3 = __shfl_sync(0xffffffffu, c, j + 3);
            float v0 = __shfl_sync(0xffffffffu, v, j + 0);
            float v1 = __shfl_sync(0xffffffffu, v, j + 1);
            float v2 = __shfl_sync(0xffffffffu, v, j + 2);
            float v3 = __shfl_sync(0xffffffffu, v, j + 3);
            float4 x0 = ((const float4*)(fb + (size_t)c0 * FD))[lane];
            float4 x1 = ((const float4*)(fb + (size_t)c1 * FD))[lane];
            float4 x2 = ((const float4*)(fb + (size_t)c2 * FD))[lane];
            float4 x3 = ((const float4*)(fb + (size_t)c3 * FD))[lane];
            acc.x += v0 * x0.x + v1 * x1.x + v2 * x2.x + v3 * x3.x;
            acc.y += v0 * x0.y + v1 * x1.y + v2 * x2.y + v3 * x3.y;
            acc.z += v0 * x0.z + v1 * x1.z + v2 * x2.z + v3 * x3.z;
            acc.w += v0 * x0.w + v1 * x1.w + v2 * x2.w + v3 * x3.w;
        }
        for (; j < cnt; j++) {
            int   cj = __shfl_sync(0xffffffffu, c, j);
            float vj = __shfl_sync(0xffffffffu, v, j);
            float4 x = ((const float4*)(fb + (size_t)cj * FD))[lane];
            acc.x += vj * x.x; acc.y += vj * x.y;
            acc.z += vj * x.z; acc.w += vj * x.w;
        }
    }
    ((float4*)(g_Lx + (size_t)r * D))[lane] = acc;
}

// ---------------------------------------------------------------------------
// Tensor-core dual-GEMM via mma.sync (bf16x3 split) + bias + leaky + L2-norm.
// Tile 128x128, 512 threads = 16 warps in 4(M)x4(N) grid, warp tile 32x32.
// Phase0: A = Lx + f, B = Wlin^T.  Phase1: A = Lx * f, B = Wint^T.
// Per phase per k16-step: Ah*Bh + Ah*Bm + Am*Bh (fp32 accum).
// ---------------------------------------------------------------------------
__global__ void __launch_bounds__(512, 1) k_gemm_mma(const float* __restrict__ blin,
                                                     const float* __restrict__ bint,
                                                     int layer) {
    extern __shared__ char dsm[];
    __shared__ float sPart[128][4];

    char* sAh = dsm;
    char* sAm = dsm + TILE_B;
    char* sBh = dsm + 2 * TILE_B;
    char* sBm = dsm + 3 * TILE_B;
    uint32_t uAh = smem_u32(sAh);
    uint32_t uAm = uAh + TILE_B;
    uint32_t uBh = uAh + 2 * TILE_B;
    uint32_t uBm = uAh + 3 * TILE_B;

    int tid = threadIdx.x;
    int wid = tid >> 5;
    int lane = tid & 31;
    int rbase = blockIdx.x * 128;
    int wm = wid & 3, wn = wid >> 2;
    int m0 = wm * 32, n0 = wn * 32;
    int g = lane >> 2, t = lane & 3;

    // Accumulators initialized with bias (col-dependent only)
    float c[2][4][4];
    #pragma unroll
    for (int j = 0; j < 4; j++) {
        int col0 = n0 + j * 8 + 2 * t;
        float b0 = blin[(size_t)layer * D + col0] + bint[(size_t)layer * D + col0];
        float b1 = blin[(size_t)layer * D + col0 + 1] + bint[(size_t)layer * D + col0 + 1];
        #pragma unroll
        for (int mt = 0; mt < 2; mt++) {
            c[mt][j][0] = b0; c[mt][j][1] = b1;
            c[mt][j][2] = b0; c[mt][j][3] = b1;
        }
    }

    // ldmatrix lane offsets (byte offsets within a tile)
    int aRow = m0 + (lane & 15);
    uint32_t aOff0 = (uint32_t)(aRow * TPITCH_B + (lane >> 4) * 16);
    uint32_t aOff1 = aOff0 + 16 * TPITCH_B;
    int bRow = n0 + ((lane >> 4) << 3) + (lane & 7);
    uint32_t bOff0 = (uint32_t)(bRow * TPITCH_B + ((lane >> 3) & 1) * 16);
    uint32_t bOff1 = bOff0 + 16 * TPITCH_B;

    #pragma unroll 1
    for (int phase = 0; phase < 2; phase++) {
        // ---- A fill: hi/mid bf16, row pitch 272B ----
        for (int gg = tid; gg < 2048; gg += 512) {
            int m = gg >> 4;
            int kg = (gg & 15) << 3;
            int r = rbase + m;
            float x[8];
            if (r < NTOT) {
                const float4* lp4 = (const float4*)(g_Lx + (size_t)r * D + kg);
                const float4* fp4 = (const float4*)(g_final + (size_t)r * FD + (size_t)layer * D + kg);
                float4 l0 = lp4[0], l1 = lp4[1];
                float4 f0 = fp4[0], f1 = fp4[1];
                if (phase == 0) {
                    x[0] = l0.x + f0.x; x[1] = l0.y + f0.y; x[2] = l0.z + f0.z; x[3] = l0.w + f0.w;
                    x[4] = l1.x + f1.x; x[5] = l1.y + f1.y; x[6] = l1.z + f1.z; x[7] = l1.w + f1.w;
                } else {
                    x[0] = l0.x * f0.x; x[1] = l0.y * f0.y; x[2] = l0.z * f0.z; x[3] = l0.w * f0.w;
                    x[4] = l1.x * f1.x; x[5] = l1.y * f1.y; x[6] = l1.z * f1.z; x[7] = l1.w * f1.w;
                }
            } else {
                #pragma unroll
                for (int jq = 0; jq < 8; jq++) x[jq] = 0.f;
            }
            uint32_t hp[4], mp[4];
            #pragma unroll
            for (int jq = 0; jq < 4; jq++) {
                float a0 = x[2 * jq], a1 = x[2 * jq + 1];
                __nv_bfloat16 h0 = __float2bfloat16(a0);
                __nv_bfloat16 h1 = __float2bfloat16(a1);
                __nv_bfloat16 mm0 = __float2bfloat16(a0 - __bfloat162float(h0));
                __nv_bfloat16 mm1 = __float2bfloat16(a1 - __bfloat162float(h1));
                hp[jq] = pack2(h0, h1);
                mp[jq] = pack2(mm0, mm1);
            }
            int off = m * TPITCH_B + kg * 2;   // 16B-aligned (272 = 17*16)
            *(uint4*)(sAh + off) = make_uint4(hp[0], hp[1], hp[2], hp[3]);
            *(uint4*)(sAm + off) = make_uint4(mp[0], mp[1], mp[2], mp[3]);
        }
        // ---- B copy from precomputed images ----
        {
            const uint32_t* srcH = g_wimg + ((size_t)(layer * 2 + phase) * 2 + 0) * 8192;
            const uint32_t* srcM = g_wimg + ((size_t)(layer * 2 + phase) * 2 + 1) * 8192;
            for (int i = tid; i < 2048; i += 512) {
                int n = i >> 4;
                int jj = i & 15;
                int off = n * TPITCH_B + jj * 16;
                *(uint4*)(sBh + off) = ((const uint4*)(srcH + n * 64))[jj];
                *(uint4*)(sBm + off) = ((const uint4*)(srcM + n * 64))[jj];
            }
        }
        __syncthreads();

        // ---- MMA mainloop ----
        #pragma unroll
        for (int ks = 0; ks < 8; ks++) {
            uint32_t kb = (uint32_t)(ks * 32);
            uint32_t ah[2][4], am[2][4], bh[2][4], bm[2][4];
            ldsm4(ah[0], uAh + aOff0 + kb);
            ldsm4(ah[1], uAh + aOff1 + kb);
            ldsm4(am[0], uAm + aOff0 + kb);
            ldsm4(am[1], uAm + aOff1 + kb);
            ldsm4(bh[0], uBh + bOff0 + kb);
            ldsm4(bh[1], uBh + bOff1 + kb);
            ldsm4(bm[0], uBm + bOff0 + kb);
            ldsm4(bm[1], uBm + bOff1 + kb);
            #pragma unroll
            for (int mt = 0; mt < 2; mt++) {
                #pragma unroll
                for (int j = 0; j < 4; j++) {
                    uint32_t bh0 = bh[j >> 1][(j & 1) * 2], bh1 = bh[j >> 1][(j & 1) * 2 + 1];
                    uint32_t bm0 = bm[j >> 1][(j & 1) * 2], bm1 = bm[j >> 1][(j & 1) * 2 + 1];
                    mma16816(c[mt][j], ah[mt], bh0, bh1);
                    mma16816(c[mt][j], ah[mt], bm0, bm1);
                    mma16816(c[mt][j], am[mt], bh0, bh1);
                }
            }
        }
        __syncthreads();  // done reading tiles before next phase refill
    }

    // ---- Epilogue: leaky_relu, cross-warp row norms, store ----
    #pragma unroll
    for (int mt = 0; mt < 2; mt++)
        #pragma unroll
        for (int j = 0; j < 4; j++)
            #pragma unroll
            for (int q = 0; q < 4; q++) {
                float v = c[mt][j][q];
                c[mt][j][q] = v > 0.f ? v : 0.01f * v;
            }

    float ss[2][2] = {{0.f, 0.f}, {0.f, 0.f}};
    #pragma unroll
    for (int mt = 0; mt < 2; mt++)
        #pragma unroll
        for (int j = 0; j < 4; j++) {
            ss[mt][0] += c[mt][j][0] * c[mt][j][0] + c[mt][j][1] * c[mt][j][1];
            ss[mt][1] += c[mt][j][2] * c[mt][j][2] + c[mt][j][3] * c[mt][j][3];
        }
    #pragma unroll
    for (int o = 1; o <= 2; o <<= 1) {
        #pragma unroll
        for (int mt = 0; mt < 2; mt++) {
            ss[mt][0] += __shfl_xor_sync(0xffffffffu, ss[mt][0], o);
            ss[mt][1] += __shfl_xor_sync(0xffffffffu, ss[mt][1], o);
        }
    }
    if (t == 0) {
        #pragma unroll
        for (int mt = 0; mt < 2; mt++) {
            sPart[m0 + mt * 16 + g][wn] = ss[mt][0];
            sPart[m0 + mt * 16 + g + 8][wn] = ss[mt][1];
        }
    }
    __syncthreads();

    #pragma unroll
    for (int mt = 0; mt < 2; mt++) {
        #pragma unroll
        for (int h = 0; h < 2; h++) {
            int row = m0 + mt * 16 + g + h * 8;
            float tot = sPart[row][0] + sPart[row][1] + sPart[row][2] + sPart[row][3];
            float scale = 1.0f / fmaxf(sqrtf(tot), 1e-12f);
            int rg = rbase + row;
            if (rg < NTOT) {
                float* dst = g_final + (size_t)rg * FD + (size_t)(layer + 1) * D;
                #pragma unroll
                for (int j = 0; j < 4; j++) {
                    int col0 = n0 + j * 8 + 2 * t;
                    float2 v = make_float2(c[mt][j][h * 2] * scale, c[mt][j][h * 2 + 1] * scale);
                    *(float2*)(dst + col0) = v;
                }
            }
        }
    }
}

// ---------------------------------------------------------------------------
// Final dot
// ---------------------------------------------------------------------------
__global__ void k_dot(const int* __restrict__ uIdx, const int* __restrict__ iIdx,
                      float* __restrict__ out) {
    int b = blockIdx.x * (blockDim.x >> 5) + (threadIdx.x >> 5);
    if (b >= BATCH) return;
    int lane = threadIdx.x & 31;
    int u = uIdx[b];
    int it = iIdx[b] + NUM_USERS;
    const float4* pu = (const float4*)(g_final + (size_t)u * FD);
    const float4* pi = (const float4*)(g_final + (size_t)it * FD);
    float s = 0.f;
    #pragma unroll
    for (int q = 0; q < 4; q++) {
        float4 a = pu[lane + 32 * q];
        float4 c = pi[lane + 32 * q];
        s += a.x * c.x + a.y * c.y + a.z * c.z + a.w * c.w;
    }
    #pragma unroll
    for (int o = 16; o > 0; o >>= 1)
        s += __shfl_xor_sync(0xffffffffu, s, o);
    if (lane == 0) out[b] = s;
}

// ---------------------------------------------------------------------------
extern "C" void kernel_launch(void* const* d_in, const int* in_sizes, int n_in,
                              void* d_out, int out_size) {
    const int*   userIdx = (const int*)d_in[0];
    const int*   itemIdx = (const int*)d_in[1];
    const int*   rows    = (const int*)d_in[2];
    const int*   cols    = (const int*)d_in[3];
    const float* vals    = (const float*)d_in[4];
    const float* uE      = (const float*)d_in[5];
    const float* iE      = (const float*)d_in[6];
    const float* Wlin    = (const float*)d_in[7];
    const float* blin    = (const float*)d_in[8];
    const float* Wint    = (const float*)d_in[9];
    const float* bint    = (const float*)d_in[10];
    float* out = (float*)d_out;

    const int smem_mma = 4 * TILE_B;  // 139264 B
    cudaFuncSetAttribute(k_gemm_mma, cudaFuncAttributeMaxDynamicSharedMemorySize, smem_mma);

    const int vec_total = NTOT * (D / 4);
    k_init<<<(vec_total + 255) / 256, 256>>>(uE, iE);
    k_wsplit<<<(3 * 2 * 128 * 64 + 255) / 256, 256>>>(Wlin, Wint);

    // CSR build (once per launch)
    k_zero_cnt<<<(NTOT + 255) / 256, 256>>>();
    k_count<<<(NNZ + 255) / 256, 256>>>(rows);
    k_scan1<<<SCAN_NB, 256>>>();
    k_scan2<<<1, 128>>>();
    k_scan3<<<(NTOT + 255) / 256, 256>>>();
    k_scatter<<<(NNZ + 255) / 256, 256>>>(rows, cols, vals);

    for (int l = 0; l < NLAYERS; l++) {
        k_spmm_csr<<<(NTOT + 7) / 8, 256>>>(l);
        k_gemm_mma<<<(NTOT + 127) / 128, 512, smem_mma>>>(blin, bint, l);
    }

    k_dot<<<(BATCH + 7) / 8, 256>>>(userIdx, itemIdx, out);
}